// round 13
// baseline (speedup 1.0000x reference)
#include <cuda_runtime.h>
#include <math.h>

#define NE 8      // experts
#define ND 16     // robot_state_size
#define NF 16     // freq bands
#define NH 512    // hidden
#define NG 16     // gate input
#define NB 8192   // batch
#define TWO_PI 6.283185307179586f

// ---------------- device scratch (no dynamic alloc allowed) ----------------
__device__ int   g_count[NE];
__device__ int   g_rows[NE * NB];
__device__ float g_gate[NE * NB];
__device__ __align__(16) float g_mid[(size_t)NE * NB * NH];   // 128 MB

// Abramowitz-Stegun 7.1.26 erf (|abs err| <= 1.5e-7) -> exact-gelu to ~1e-6
__device__ __forceinline__ float fast_gelu(float x) {
    float u = 0.70710678118654752f * x;
    float a = fabsf(u);
    float t = __fdividef(1.0f, fmaf(0.3275911f, a, 1.0f));
    float poly = t * fmaf(t, fmaf(t, fmaf(t, fmaf(t, 1.061405429f, -1.453152027f),
                                          1.421413741f), -0.284496736f), 0.254829592f);
    float e = __expf(-u * u);
    float erfa = fmaf(-poly, e, 1.0f);
    float erfu = copysignf(erfa, x);
    return 0.5f * x * (1.0f + erfu);
}

__device__ __forceinline__ unsigned f2tf32(float f) {
    unsigned r;
    asm("cvt.rna.tf32.f32 %0, %1;" : "=r"(r) : "f"(f));
    return r;
}

__device__ __forceinline__ void mma_tf32(float* c, const unsigned* a, const unsigned* b) {
    asm volatile(
        "mma.sync.aligned.m16n8k8.row.col.f32.tf32.tf32.f32 "
        "{%0,%1,%2,%3}, {%4,%5,%6,%7}, {%8,%9}, {%0,%1,%2,%3};\n"
        : "+f"(c[0]), "+f"(c[1]), "+f"(c[2]), "+f"(c[3])
        : "r"(a[0]), "r"(a[1]), "r"(a[2]), "r"(a[3]), "r"(b[0]), "r"(b[1]));
}

// ---------------- init: zero output buffer + expert counters ----------------
__global__ void k_init(float* __restrict__ out, int out_size) {
    int idx = blockIdx.x * blockDim.x + threadIdx.x;
    if (idx < NE) g_count[idx] = 0;
    int n4 = out_size >> 2;
    float4* o4 = (float4*)out;
    for (int i = idx; i < n4; i += gridDim.x * blockDim.x)
        o4[i] = make_float4(0.f, 0.f, 0.f, 0.f);
    if (idx < (out_size & 3)) out[n4 * 4 + idx] = 0.0f;
}

// ---------------- gate: logits -> softmax -> top2 -> renorm -> scatter ------
__global__ void k_gate(const float* __restrict__ gin, const int* __restrict__ task_p,
                       const float* __restrict__ gw, const float* __restrict__ gb) {
    __shared__ float sw[NG * NE];
    __shared__ float sb[NE];
    int task = task_p[0];
    for (int i = threadIdx.x; i < NG * NE; i += blockDim.x)
        sw[i] = gw[task * NG * NE + i];
    if (threadIdx.x < NE) sb[threadIdx.x] = gb[task * NE + threadIdx.x];
    __syncthreads();

    int b = blockIdx.x * blockDim.x + threadIdx.x;
    if (b >= NB) return;

    float x[NG];
#pragma unroll
    for (int g = 0; g < NG; g++) x[g] = gin[b * NG + g];

    float lg[NE];
#pragma unroll
    for (int e = 0; e < NE; e++) {
        float s = sb[e];
#pragma unroll
        for (int g = 0; g < NG; g++) s += x[g] * sw[g * NE + e];
        lg[e] = s;
    }
    float m = lg[0];
#pragma unroll
    for (int e = 1; e < NE; e++) m = fmaxf(m, lg[e]);
    float p[NE];
#pragma unroll
    for (int e = 0; e < NE; e++) p[e] = expf(lg[e] - m);

    // top-2 (ties -> lower index, matching lax.top_k)
    int i0 = 0; float v0 = p[0];
#pragma unroll
    for (int e = 1; e < NE; e++) if (p[e] > v0) { v0 = p[e]; i0 = e; }
    int i1 = (i0 == 0) ? 1 : 0; float v1 = p[i1];
#pragma unroll
    for (int e = 0; e < NE; e++) if (e != i0 && p[e] > v1) { v1 = p[e]; i1 = e; }

    float inv = 1.0f / (v0 + v1);   // softmax denom cancels in the ratio
    v0 *= inv; v1 *= inv;

    int p0 = atomicAdd(&g_count[i0], 1);
    g_rows[i0 * NB + p0] = b; g_gate[i0 * NB + p0] = v0;
    int p1 = atomicAdd(&g_count[i1], 1);
    g_rows[i1 * NB + p1] = b; g_gate[i1 * NB + p1] = v1;
}

// ---------------- stage 1 (TF32 tensor cores, dynamic smem) -----------------
// h[32 slots, 512] = feat[32,33] @ w1[e,d][33,512] + b1 ; LN; gelu; sum over d.
// CTA = 8 warps; warp = 16 slots (sg) x 128 cols (cg). K=32 via 4 mma k-frags;
// identity row (k=32) + bias as scalar epilogue. LN via frag shuffles + smem.
// Dynamic smem layout (bytes):
//   xs  @ 0      : float[32][17]      = 2176
//   fa  @ 2176   : float[32][36]      = 4608
//   ws  @ 6784   : unsigned[36][520]  = 74880
//   red @ 81664  : float[2][4][8][4]  = 1024
//   total 82688
#define S1S 32
#define S1_SMEM 82688
__global__ __launch_bounds__(256, 1) void k_stage1(
    const float* __restrict__ xin,  const float* __restrict__ freqs,
    const float* __restrict__ w1,   const float* __restrict__ b1,
    const float* __restrict__ lng,  const float* __restrict__ lnb) {
    int e = blockIdx.y;
    int cnt = g_count[e];
    int base = blockIdx.x * S1S;
    if (base >= cnt) return;

    extern __shared__ __align__(16) unsigned char s1mem[];
    float    (*xs)[17]        = (float(*)[17])(s1mem);
    float    (*fa)[36]        = (float(*)[36])(s1mem + 2176);
    unsigned (*ws)[520]       = (unsigned(*)[520])(s1mem + 6784);
    float    (*red)[4][8][4]  = (float(*)[4][8][4])(s1mem + 81664);

    int tid = threadIdx.x;
    int warp = tid >> 5, lane = tid & 31;
    int sg = warp >> 2;          // slot group: slots [sg*16, +16)
    int cg = warp & 3;           // col group:  cols  [cg*128, +128)
    int crow = lane >> 2;        // frag row (and +8)
    int acol = lane & 3;         // A col / B row within k-frag
    int bcol = lane >> 2;        // B col within n-frag
    int ccol = (lane & 3) * 2;   // C col (and +1)

    if (tid < S1S) {
        int s = base + tid;
        int row = (s < cnt) ? g_rows[e * NB + s] : g_rows[e * NB];
        const float4* xr = (const float4*)(xin + (size_t)row * ND);
        float4 v0 = xr[0], v1 = xr[1], v2 = xr[2], v3 = xr[3];
        xs[tid][0] = v0.x; xs[tid][1] = v0.y; xs[tid][2] = v0.z; xs[tid][3] = v0.w;
        xs[tid][4] = v1.x; xs[tid][5] = v1.y; xs[tid][6] = v1.z; xs[tid][7] = v1.w;
        xs[tid][8] = v2.x; xs[tid][9] = v2.y; xs[tid][10] = v2.z; xs[tid][11] = v2.w;
        xs[tid][12] = v3.x; xs[tid][13] = v3.y; xs[tid][14] = v3.z; xs[tid][15] = v3.w;
    }

    float acc[16][4];
#pragma unroll
    for (int nf = 0; nf < 16; nf++)
#pragma unroll
        for (int q = 0; q < 4; q++) acc[nf][q] = 0.0f;

    const float* w1e = w1   + (size_t)e * ND * 33 * NH;
    const float* b1e = b1   + (size_t)e * ND * NH;
    const float* lge = lng  + (size_t)e * ND * NH;
    const float* lbe = lnb  + (size_t)e * ND * NH;
    const float* fre = freqs + (size_t)e * ND * NF;

#pragma unroll 1
    for (int d = 0; d < ND; d++) {
        __syncthreads();   // previous iteration's fa/ws/red readers are done

        // ---- feat: 32 slots x 16 freqs, 2 per thread ----
        {
            int idx = tid;
#pragma unroll
            for (int it = 0; it < 2; it++) {
                int slot = idx & 31, k = idx >> 5;
                float ang = xs[slot][d] * __ldg(&fre[d * NF + k]) * TWO_PI;
                float sv, cv;
                __sincosf(ang, &sv, &cv);
                fa[slot][k] = cv;
                fa[slot][16 + k] = sv;
                idx += 256;
            }
            if (tid < S1S) fa[tid][32] = xs[tid][d];
        }

        // ---- stage ws: rows 0-32 = w1[d] (0-31 tf32, 32 raw), 33 b1, 34 lng, 35 lnb
        {
            const float* w1d = w1e + (size_t)d * 33 * NH;
#pragma unroll 1
            for (int q = tid; q < 36 * 128; q += 256) {
                int r = q >> 7, c4 = (q & 127) * 4;
                const float* src = (r < 33) ? (w1d + r * NH + c4)
                                 : (r == 33) ? (b1e + (size_t)d * NH + c4)
                                 : (r == 34) ? (lge + (size_t)d * NH + c4)
                                             : (lbe + (size_t)d * NH + c4);
                float4 v = __ldg((const float4*)src);
                uint4 u;
                if (r < 32) {
                    u.x = f2tf32(v.x); u.y = f2tf32(v.y);
                    u.z = f2tf32(v.z); u.w = f2tf32(v.w);
                } else {
                    u.x = __float_as_uint(v.x); u.y = __float_as_uint(v.y);
                    u.z = __float_as_uint(v.z); u.w = __float_as_uint(v.w);
                }
                *(uint4*)&ws[r][c4] = u;
            }
        }
        __syncthreads();

        // ---- A frags (tf32 from fa) ----
        unsigned a[4][4];
#pragma unroll
        for (int kf = 0; kf < 4; kf++) {
            int kc = kf * 8;
            a[kf][0] = f2tf32(fa[sg * 16 + crow    ][kc + acol    ]);
            a[kf][1] = f2tf32(fa[sg * 16 + crow + 8][kc + acol    ]);
            a[kf][2] = f2tf32(fa[sg * 16 + crow    ][kc + acol + 4]);
            a[kf][3] = f2tf32(fa[sg * 16 + crow + 8][kc + acol + 4]);
        }

        float C[16][4];
#pragma unroll
        for (int nf = 0; nf < 16; nf++)
#pragma unroll
            for (int q = 0; q < 4; q++) C[nf][q] = 0.0f;

#pragma unroll
        for (int kf = 0; kf < 4; kf++) {
            int kc = kf * 8;
#pragma unroll
            for (int nf = 0; nf < 16; nf++) {
                int n = cg * 128 + nf * 8 + bcol;
                unsigned bfr[2];
                bfr[0] = ws[kc + acol    ][n];
                bfr[1] = ws[kc + acol + 4][n];
                mma_tf32(C[nf], a[kf], bfr);
            }
        }

        // ---- identity row (k=32) + bias, in fp32 ----
        float x0 = fa[sg * 16 + crow][32];
        float x1 = fa[sg * 16 + crow + 8][32];
#pragma unroll
        for (int nf = 0; nf < 16; nf++) {
            int c0 = cg * 128 + nf * 8 + ccol;
            float2 w32 = *(const float2*)&ws[32][c0];
            float2 bb  = *(const float2*)&ws[33][c0];
            C[nf][0] = fmaf(x0, w32.x, C[nf][0] + bb.x);
            C[nf][1] = fmaf(x0, w32.y, C[nf][1] + bb.y);
            C[nf][2] = fmaf(x1, w32.x, C[nf][2] + bb.x);
            C[nf][3] = fmaf(x1, w32.y, C[nf][3] + bb.y);
        }

        // ---- LN stats: rows sg*16+crow (a) and +8 (b) ----
        float s1a = 0.f, s2a = 0.f, s1b = 0.f, s2b = 0.f;
#pragma unroll
        for (int nf = 0; nf < 16; nf++) {
            s1a += C[nf][0] + C[nf][1];
            s2a += C[nf][0] * C[nf][0] + C[nf][1] * C[nf][1];
            s1b += C[nf][2] + C[nf][3];
            s2b += C[nf][2] * C[nf][2] + C[nf][3] * C[nf][3];
        }
#pragma unroll
        for (int o = 1; o <= 2; o <<= 1) {
            s1a += __shfl_xor_sync(0xffffffffu, s1a, o);
            s2a += __shfl_xor_sync(0xffffffffu, s2a, o);
            s1b += __shfl_xor_sync(0xffffffffu, s1b, o);
            s2b += __shfl_xor_sync(0xffffffffu, s2b, o);
        }
        if ((lane & 3) == 0)
            *(float4*)&red[sg][cg][crow][0] = make_float4(s1a, s2a, s1b, s2b);
        __syncthreads();

        float4 r0 = *(const float4*)&red[sg][0][crow][0];
        float4 r1 = *(const float4*)&red[sg][1][crow][0];
        float4 r2 = *(const float4*)&red[sg][2][crow][0];
        float4 r3 = *(const float4*)&red[sg][3][crow][0];
        float t1a = r0.x + r1.x + r2.x + r3.x;
        float t2a = r0.y + r1.y + r2.y + r3.y;
        float t1b = r0.z + r1.z + r2.z + r3.z;
        float t2b = r0.w + r1.w + r2.w + r3.w;
        float mu_a = t1a * (1.0f / NH);
        float va   = t2a * (1.0f / NH) - mu_a * mu_a;
        float rs_a = rsqrtf(va + 1e-5f);
        float mu_b = t1b * (1.0f / NH);
        float vb   = t2b * (1.0f / NH) - mu_b * mu_b;
        float rs_b = rsqrtf(vb + 1e-5f);

        // ---- gelu + accumulate over d ----
#pragma unroll
        for (int nf = 0; nf < 16; nf++) {
            int c0 = cg * 128 + nf * 8 + ccol;
            float2 gv = *(const float2*)&ws[34][c0];
            float2 ov = *(const float2*)&ws[35][c0];
            acc[nf][0] += fast_gelu((C[nf][0] - mu_a) * rs_a * gv.x + ov.x);
            acc[nf][1] += fast_gelu((C[nf][1] - mu_a) * rs_a * gv.y + ov.y);
            acc[nf][2] += fast_gelu((C[nf][2] - mu_b) * rs_b * gv.x + ov.x);
            acc[nf][3] += fast_gelu((C[nf][3] - mu_b) * rs_b * gv.y + ov.y);
        }
    }

    // ---- write acc -> g_mid ----
    int s0 = base + sg * 16 + crow;
    int s1r = s0 + 8;
#pragma unroll
    for (int nf = 0; nf < 16; nf++) {
        int c0 = cg * 128 + nf * 8 + ccol;
        if (s0 < cnt)
            *(float2*)&g_mid[(size_t)(e * NB + s0) * NH + c0] =
                make_float2(acc[nf][0], acc[nf][1]);
        if (s1r < cnt)
            *(float2*)&g_mid[(size_t)(e * NB + s1r) * NH + c0] =
                make_float2(acc[nf][2], acc[nf][3]);
    }
}

// ---------------- stage 2: per-expert GEMM via TF32 mma.sync (R11, kept) ----
#define BM 128
#define BN 128
#define BK 16
__global__ __launch_bounds__(256, 2) void k_stage2(
    const float* __restrict__ wo, const float* __restrict__ bo,
    float* __restrict__ out) {
    int e = blockIdx.z;
    int cnt = g_count[e];
    int rowbase = blockIdx.x * BM;
    if (rowbase >= cnt) return;
    int colbase = blockIdx.y * BN;

    __shared__ unsigned As[2][BK][BM + 4];
    __shared__ unsigned Bs[2][BK][BN + 4];

    int tid = threadIdx.x;
    int warp = tid >> 5, lane = tid & 31;
    int wm = warp >> 1, wn = warp & 1;

    float C[2][8][4];
#pragma unroll
    for (int mi = 0; mi < 2; mi++)
#pragma unroll
        for (int ni = 0; ni < 8; ni++)
#pragma unroll
            for (int q = 0; q < 4; q++) C[mi][ni][q] = 0.0f;

    const float* mide = g_mid + (size_t)e * NB * NH;
    const float* woe  = wo + (size_t)e * NH * NH;

    int a_r  = tid >> 2, a_kq = tid & 3;
    int b_c4 = tid & 31, b_kk = tid >> 5;
    int gr0 = rowbase + a_r, gr1 = gr0 + 64;

    float4 pa[2], pb[2];
    pa[0] = (gr0 < cnt) ? *(const float4*)(mide + (size_t)gr0 * NH + a_kq * 4)
                        : make_float4(0.f, 0.f, 0.f, 0.f);
    pa[1] = (gr1 < cnt) ? *(const float4*)(mide + (size_t)gr1 * NH + a_kq * 4)
                        : make_float4(0.f, 0.f, 0.f, 0.f);
    pb[0] = *(const float4*)(woe + (size_t)b_kk * NH + colbase + b_c4 * 4);
    pb[1] = *(const float4*)(woe + (size_t)(b_kk + 8) * NH + colbase + b_c4 * 4);
#pragma unroll
    for (int q = 0; q < 2; q++) {
        int r = (q == 0) ? a_r : a_r + 64;
        As[0][a_kq * 4 + 0][r] = f2tf32(q == 0 ? pa[0].x : pa[1].x);
        As[0][a_kq * 4 + 1][r] = f2tf32(q == 0 ? pa[0].y : pa[1].y);
        As[0][a_kq * 4 + 2][r] = f2tf32(q == 0 ? pa[0].z : pa[1].z);
        As[0][a_kq * 4 + 3][r] = f2tf32(q == 0 ? pa[0].w : pa[1].w);
        int kk = (q == 0) ? b_kk : b_kk + 8;
        Bs[0][kk][b_c4 * 4 + 0] = f2tf32(q == 0 ? pb[0].x : pb[1].x);
        Bs[0][kk][b_c4 * 4 + 1] = f2tf32(q == 0 ? pb[0].y : pb[1].y);
        Bs[0][kk][b_c4 * 4 + 2] = f2tf32(q == 0 ? pb[0].z : pb[1].z);
        Bs[0][kk][b_c4 * 4 + 3] = f2tf32(q == 0 ? pb[0].w : pb[1].w);
    }
    __syncthreads();

    int arow = lane >> 2, acol = lane & 3;
    int brow = lane & 3,  bcol = lane >> 2;

#pragma unroll 1
    for (int t = 0; t < NH / BK; t++) {
        int p = t & 1;
        int k1 = (t + 1) * BK;
        bool hasnext = k1 < NH;
        if (hasnext) {
            pa[0] = (gr0 < cnt) ? *(const float4*)(mide + (size_t)gr0 * NH + k1 + a_kq * 4)
                                : make_float4(0.f, 0.f, 0.f, 0.f);
            pa[1] = (gr1 < cnt) ? *(const float4*)(mide + (size_t)gr1 * NH + k1 + a_kq * 4)
                                : make_float4(0.f, 0.f, 0.f, 0.f);
            pb[0] = *(const float4*)(woe + (size_t)(k1 + b_kk) * NH + colbase + b_c4 * 4);
            pb[1] = *(const float4*)(woe + (size_t)(k1 + b_kk + 8) * NH + colbase + b_c4 * 4);
        }

#pragma unroll
        for (int kc = 0; kc < BK; kc += 8) {
            unsigned afr[2][4];
#pragma unroll
            for (int mi = 0; mi < 2; mi++) {
                int m = wm * 32 + mi * 16 + arow;
                afr[mi][0] = As[p][kc + acol][m];
                afr[mi][1] = As[p][kc + acol][m + 8];
                afr[mi][2] = As[p][kc + acol + 4][m];
                afr[mi][3] = As[p][kc + acol + 4][m + 8];
            }
            unsigned bfr[8][2];
#pragma unroll
            for (int ni = 0; ni < 8; ni++) {
                int n = wn * 64 + ni * 8 + bcol;
                bfr[ni][0] = Bs[p][kc + brow][n];
                bfr[ni][1] = Bs[p][kc + brow + 4][n];
            }
#pragma unroll
            for (int mi = 0; mi < 2; mi++)
#pragma unroll
                for (int ni = 0; ni < 8; ni++)
                    mma_tf32(C[mi][ni], afr[mi], bfr[ni]);
        }

        if (hasnext) {
            int u = 1 - p;
#pragma unroll
            for (int q = 0; q < 2; q++) {
                int r = (q == 0) ? a_r : a_r + 64;
                As[u][a_kq * 4 + 0][r] = f2tf32(q == 0 ? pa[0].x : pa[1].x);
                As[u][a_kq * 4 + 1][r] = f2tf32(q == 0 ? pa[0].y : pa[1].y);
                As[u][a_kq * 4 + 2][r] = f2tf32(q == 0 ? pa[0].z : pa[1].z);
                As[u][a_kq * 4 + 3][r] = f2tf32(q == 0 ? pa[0].w : pa[1].w);
                int kk = (q == 0) ? b_kk : b_kk + 8;
                Bs[u][kk][b_c4 * 4 + 0] = f2tf32(q == 0 ? pb[0].x : pb[1].x);
                Bs[u][kk][b_c4 * 4 + 1] = f2tf32(q == 0 ? pb[0].y : pb[1].y);
                Bs[u][kk][b_c4 * 4 + 2] = f2tf32(q == 0 ? pb[0].z : pb[1].z);
                Bs[u][kk][b_c4 * 4 + 3] = f2tf32(q == 0 ? pb[0].w : pb[1].w);
            }
            __syncthreads();
        }
    }

    const float* boe = bo + (size_t)e * NH + colbase;
    int crow = lane >> 2, ccol = (lane & 3) * 2;
#pragma unroll
    for (int mi = 0; mi < 2; mi++) {
#pragma unroll
        for (int half = 0; half < 2; half++) {
            int r = wm * 32 + mi * 16 + crow + half * 8;
            int s = rowbase + r;
            if (s < cnt) {
                int b = g_rows[e * NB + s];
                float g = g_gate[e * NB + s];
                float* o = out + (size_t)b * NH + colbase;
#pragma unroll
                for (int ni = 0; ni < 8; ni++) {
                    int col = wn * 64 + ni * 8 + ccol;
                    float2 bo2 = __ldg((const float2*)(boe + col));
                    atomicAdd(o + col,     g * (C[mi][ni][half * 2 + 0] + bo2.x));
                    atomicAdd(o + col + 1, g * (C[mi][ni][half * 2 + 1] + bo2.y));
                }
            }
        }
    }
}

// ---------------- launch ----------------
extern "C" void kernel_launch(void* const* d_in, const int* in_sizes, int n_in,
                              void* d_out, int out_size) {
    const float* gate_input   = (const float*)d_in[0];
    const float* expert_input = (const float*)d_in[1];
    const int*   task_bh      = (const int*)  d_in[2];
    const float* gate_w       = (const float*)d_in[3];
    const float* gate_b       = (const float*)d_in[4];
    const float* freqs        = (const float*)d_in[5];
    const float* w1           = (const float*)d_in[6];
    const float* b1           = (const float*)d_in[7];
    const float* ln_g         = (const float*)d_in[8];
    const float* ln_b         = (const float*)d_in[9];
    const float* wo           = (const float*)d_in[10];
    const float* bo           = (const float*)d_in[11];
    float* out = (float*)d_out;

    // opt-in to >48KB dynamic smem for stage1 (idempotent, no allocation)
    cudaFuncSetAttribute(k_stage1, cudaFuncAttributeMaxDynamicSharedMemorySize,
                         S1_SMEM);

    k_init<<<1024, 256>>>(out, out_size);
    k_gate<<<NB / 256, 256>>>(gate_input, task_bh, gate_w, gate_b);
    k_stage1<<<dim3(NB / S1S, NE), 256, S1_SMEM>>>(expert_input, freqs, w1, b1,
                                                   ln_g, ln_b);
    k_stage2<<<dim3(NB / BM, NH / BN, NE), 256>>>(wo, bo, out);
}

// round 14
// speedup vs baseline: 1.6532x; 1.6532x over previous
#include <cuda_runtime.h>
#include <math.h>

#define NE 8      // experts
#define ND 16     // robot_state_size
#define NF 16     // freq bands
#define NH 512    // hidden
#define NG 16     // gate input
#define NB 8192   // batch
#define TWO_PI 6.283185307179586f

// ---------------- device scratch (no dynamic alloc allowed) ----------------
__device__ int   g_count[NE];
__device__ int   g_rows[NE * NB];
__device__ float g_gate[NE * NB];
__device__ __align__(16) float    g_mid[(size_t)NE * NB * NH];      // 128 MB
__device__ __align__(16) unsigned g_w1s[(size_t)NE * ND * 36 * 520]; // 9.6 MB packed

// Abramowitz-Stegun 7.1.26 erf (|abs err| <= 1.5e-7) -> exact-gelu to ~1e-6
__device__ __forceinline__ float fast_gelu(float x) {
    float u = 0.70710678118654752f * x;
    float a = fabsf(u);
    float t = __fdividef(1.0f, fmaf(0.3275911f, a, 1.0f));
    float poly = t * fmaf(t, fmaf(t, fmaf(t, fmaf(t, 1.061405429f, -1.453152027f),
                                          1.421413741f), -0.284496736f), 0.254829592f);
    float e = __expf(-u * u);
    float erfa = fmaf(-poly, e, 1.0f);
    float erfu = copysignf(erfa, x);
    return 0.5f * x * (1.0f + erfu);
}

__device__ __forceinline__ unsigned f2tf32(float f) {
    unsigned r;
    asm("cvt.rna.tf32.f32 %0, %1;" : "=r"(r) : "f"(f));
    return r;
}

__device__ __forceinline__ void mma_tf32(float* c, const unsigned* a, const unsigned* b) {
    asm volatile(
        "mma.sync.aligned.m16n8k8.row.col.f32.tf32.tf32.f32 "
        "{%0,%1,%2,%3}, {%4,%5,%6,%7}, {%8,%9}, {%0,%1,%2,%3};\n"
        : "+f"(c[0]), "+f"(c[1]), "+f"(c[2]), "+f"(c[3])
        : "r"(a[0]), "r"(a[1]), "r"(a[2]), "r"(a[3]), "r"(b[0]), "r"(b[1]));
}

__device__ __forceinline__ void cp_async16(unsigned smem_addr, const void* gmem) {
    asm volatile("cp.async.cg.shared.global [%0], [%1], 16;\n"
                 :: "r"(smem_addr), "l"(gmem));
}
__device__ __forceinline__ void cp_commit() {
    asm volatile("cp.async.commit_group;\n");
}
__device__ __forceinline__ void cp_wait0() {
    asm volatile("cp.async.wait_group 0;\n");
}

// ---------------- init: zero output buffer + expert counters ----------------
__global__ void k_init(float* __restrict__ out, int out_size) {
    int idx = blockIdx.x * blockDim.x + threadIdx.x;
    if (idx < NE) g_count[idx] = 0;
    int n4 = out_size >> 2;
    float4* o4 = (float4*)out;
    for (int i = idx; i < n4; i += gridDim.x * blockDim.x)
        o4[i] = make_float4(0.f, 0.f, 0.f, 0.f);
    if (idx < (out_size & 3)) out[n4 * 4 + idx] = 0.0f;
}

// ---------------- pack: w1 -> tf32 staging layout [e][d][36][520] -----------
// rows 0-31: tf32(w1 rows 0-31); 32: raw w1 row 32; 33: b1; 34: ln_g; 35: ln_b
__global__ void k_pack(const float* __restrict__ w1, const float* __restrict__ b1,
                       const float* __restrict__ lng, const float* __restrict__ lnb) {
    int d = blockIdx.x, e = blockIdx.y;
    unsigned* dst = g_w1s + (size_t)(e * ND + d) * 36 * 520;
    const float* w1d = w1 + (size_t)(e * ND + d) * 33 * NH;
    const float* b1d = b1 + (size_t)(e * ND + d) * NH;
    const float* lgd = lng + (size_t)(e * ND + d) * NH;
    const float* lbd = lnb + (size_t)(e * ND + d) * NH;
    for (int q = threadIdx.x; q < 36 * 520; q += blockDim.x) {
        int r = q / 520, c = q - r * 520;
        unsigned v = 0;
        if (c < NH) {
            if (r < 32)      v = f2tf32(w1d[r * NH + c]);
            else if (r == 32) v = __float_as_uint(w1d[32 * NH + c]);
            else if (r == 33) v = __float_as_uint(b1d[c]);
            else if (r == 34) v = __float_as_uint(lgd[c]);
            else              v = __float_as_uint(lbd[c]);
        }
        dst[q] = v;
    }
}

// ---------------- gate: logits -> softmax -> top2 -> renorm -> scatter ------
__global__ void k_gate(const float* __restrict__ gin, const int* __restrict__ task_p,
                       const float* __restrict__ gw, const float* __restrict__ gb) {
    __shared__ float sw[NG * NE];
    __shared__ float sb[NE];
    int task = task_p[0];
    for (int i = threadIdx.x; i < NG * NE; i += blockDim.x)
        sw[i] = gw[task * NG * NE + i];
    if (threadIdx.x < NE) sb[threadIdx.x] = gb[task * NE + threadIdx.x];
    __syncthreads();

    int b = blockIdx.x * blockDim.x + threadIdx.x;
    if (b >= NB) return;

    float x[NG];
#pragma unroll
    for (int g = 0; g < NG; g++) x[g] = gin[b * NG + g];

    float lg[NE];
#pragma unroll
    for (int e = 0; e < NE; e++) {
        float s = sb[e];
#pragma unroll
        for (int g = 0; g < NG; g++) s += x[g] * sw[g * NE + e];
        lg[e] = s;
    }
    float m = lg[0];
#pragma unroll
    for (int e = 1; e < NE; e++) m = fmaxf(m, lg[e]);
    float p[NE];
#pragma unroll
    for (int e = 0; e < NE; e++) p[e] = expf(lg[e] - m);

    // top-2 (ties -> lower index, matching lax.top_k)
    int i0 = 0; float v0 = p[0];
#pragma unroll
    for (int e = 1; e < NE; e++) if (p[e] > v0) { v0 = p[e]; i0 = e; }
    int i1 = (i0 == 0) ? 1 : 0; float v1 = p[i1];
#pragma unroll
    for (int e = 0; e < NE; e++) if (e != i0 && p[e] > v1) { v1 = p[e]; i1 = e; }

    float inv = 1.0f / (v0 + v1);   // softmax denom cancels in the ratio
    v0 *= inv; v1 *= inv;

    int p0 = atomicAdd(&g_count[i0], 1);
    g_rows[i0 * NB + p0] = b; g_gate[i0 * NB + p0] = v0;
    int p1 = atomicAdd(&g_count[i1], 1);
    g_rows[i1 * NB + p1] = b; g_gate[i1 * NB + p1] = v1;
}

// ---------------- stage 1 (TF32 mma, cp.async double-buffered weights) ------
// h[32 slots, 512] = feat[32,33] @ w1[e,d][33,512] + b1 ; LN; gelu; sum over d.
// CTA = 8 warps; warp = 16 slots (sg) x 128 cols (cg). feat built in registers
// (8 __sincosf/thread/d). Weights cp.async'd from pre-packed g_w1s, 2 buffers.
// Dyn smem: ws2[2][36*520]u32 @0 (149760) ; xs[32][17] @149760 (2176) ;
//           red[2][4][8][4] @151936 (1024) ; total 152960.
#define S1S 32
#define S1_WSB 74880
#define S1_SMEM 152960
__global__ __launch_bounds__(256, 1) void k_stage1(
    const float* __restrict__ xin,  const float* __restrict__ freqs,
    const float* __restrict__ w1_unused) {
    int e = blockIdx.y;
    int cnt = g_count[e];
    int base = blockIdx.x * S1S;
    if (base >= cnt) return;

    extern __shared__ __align__(16) unsigned char s1mem[];
    float (*xs)[17]       = (float(*)[17])(s1mem + 2 * S1_WSB);
    float (*red)[4][8][4] = (float(*)[4][8][4])(s1mem + 2 * S1_WSB + 2176);
    unsigned ws_smem_base = (unsigned)__cvta_generic_to_shared(s1mem);

    int tid = threadIdx.x;
    int warp = tid >> 5, lane = tid & 31;
    int sg = warp >> 2;          // slot group: slots [sg*16, +16)
    int cg = warp & 3;           // col group:  cols  [cg*128, +128)
    int crow = lane >> 2;        // frag rows r0, r0+8
    int acol = lane & 3;         // A col / B row within k-frag
    int bcol = lane >> 2;        // B col within n-frag
    int ccol = (lane & 3) * 2;   // C col (and +1)
    int r0 = sg * 16 + crow;

    if (tid < S1S) {
        int s = base + tid;
        int row = (s < cnt) ? g_rows[e * NB + s] : g_rows[e * NB];
        const float4* xr = (const float4*)(xin + (size_t)row * ND);
        float4 v0 = xr[0], v1 = xr[1], v2 = xr[2], v3 = xr[3];
        xs[tid][0] = v0.x; xs[tid][1] = v0.y; xs[tid][2] = v0.z; xs[tid][3] = v0.w;
        xs[tid][4] = v1.x; xs[tid][5] = v1.y; xs[tid][6] = v1.z; xs[tid][7] = v1.w;
        xs[tid][8] = v2.x; xs[tid][9] = v2.y; xs[tid][10] = v2.z; xs[tid][11] = v2.w;
        xs[tid][12] = v3.x; xs[tid][13] = v3.y; xs[tid][14] = v3.z; xs[tid][15] = v3.w;
    }

    float acc[16][4];
#pragma unroll
    for (int nf = 0; nf < 16; nf++)
#pragma unroll
        for (int q = 0; q < 4; q++) acc[nf][q] = 0.0f;

    const float*    fre = freqs + (size_t)e * ND * NF;
    const unsigned* wse = g_w1s + (size_t)e * ND * 36 * 520;

    // prologue: stage d=0 into buffer 0
    {
        const uint4* src = (const uint4*)wse;   // d = 0
#pragma unroll 1
        for (int q = tid; q < 4680; q += 256)
            cp_async16(ws_smem_base + q * 16, src + q);
        cp_commit();
    }

#pragma unroll 1
    for (int d = 0; d < ND; d++) {
        int p = d & 1;
        cp_wait0();
        __syncthreads();   // buffer p ready everywhere; prev iter fully done

        // prefetch d+1 into buffer 1-p (background)
        if (d + 1 < ND) {
            const uint4* src = (const uint4*)(wse + (size_t)(d + 1) * 36 * 520);
            unsigned dstb = ws_smem_base + (1 - p) * S1_WSB;
#pragma unroll 1
            for (int q = tid; q < 4680; q += 256)
                cp_async16(dstb + q * 16, src + q);
            cp_commit();
        }

        const unsigned (*ws)[520] = (const unsigned(*)[520])(s1mem + p * S1_WSB);

        // ---- A frags in registers: 4 angles per row, cos->kf0/1, sin->kf2/3
        float x0 = xs[r0][d];
        float x1 = xs[r0 + 8][d];
        float f0 = __ldg(&fre[d * NF + acol]);
        float f1 = __ldg(&fre[d * NF + acol + 4]);
        float f2v = __ldg(&fre[d * NF + acol + 8]);
        float f3v = __ldg(&fre[d * NF + acol + 12]);
        float s00, c00, s01, c01, s02, c02, s03, c03;
        float s10, c10, s11, c11, s12, c12, s13, c13;
        __sincosf(x0 * f0 * TWO_PI, &s00, &c00);
        __sincosf(x0 * f1 * TWO_PI, &s01, &c01);
        __sincosf(x0 * f2v * TWO_PI, &s02, &c02);
        __sincosf(x0 * f3v * TWO_PI, &s03, &c03);
        __sincosf(x1 * f0 * TWO_PI, &s10, &c10);
        __sincosf(x1 * f1 * TWO_PI, &s11, &c11);
        __sincosf(x1 * f2v * TWO_PI, &s12, &c12);
        __sincosf(x1 * f3v * TWO_PI, &s13, &c13);
        unsigned a[4][4];
        a[0][0] = f2tf32(c00); a[0][1] = f2tf32(c10); a[0][2] = f2tf32(c01); a[0][3] = f2tf32(c11);
        a[1][0] = f2tf32(c02); a[1][1] = f2tf32(c12); a[1][2] = f2tf32(c03); a[1][3] = f2tf32(c13);
        a[2][0] = f2tf32(s00); a[2][1] = f2tf32(s10); a[2][2] = f2tf32(s01); a[2][3] = f2tf32(s11);
        a[3][0] = f2tf32(s02); a[3][1] = f2tf32(s12); a[3][2] = f2tf32(s03); a[3][3] = f2tf32(s13);

        float C[16][4];
#pragma unroll
        for (int nf = 0; nf < 16; nf++)
#pragma unroll
            for (int q = 0; q < 4; q++) C[nf][q] = 0.0f;

#pragma unroll
        for (int kf = 0; kf < 4; kf++) {
            int kc = kf * 8;
#pragma unroll
            for (int nf = 0; nf < 16; nf++) {
                int n = cg * 128 + nf * 8 + bcol;
                unsigned bfr[2];
                bfr[0] = ws[kc + acol    ][n];
                bfr[1] = ws[kc + acol + 4][n];
                mma_tf32(C[nf], a[kf], bfr);
            }
        }

        // ---- identity row (k=32) + bias, in fp32 ----
#pragma unroll
        for (int nf = 0; nf < 16; nf++) {
            int c0 = cg * 128 + nf * 8 + ccol;
            float2 w32 = *(const float2*)&ws[32][c0];
            float2 bb  = *(const float2*)&ws[33][c0];
            C[nf][0] = fmaf(x0, w32.x, C[nf][0] + bb.x);
            C[nf][1] = fmaf(x0, w32.y, C[nf][1] + bb.y);
            C[nf][2] = fmaf(x1, w32.x, C[nf][2] + bb.x);
            C[nf][3] = fmaf(x1, w32.y, C[nf][3] + bb.y);
        }

        // ---- LN stats: rows r0 (a) and r0+8 (b) ----
        float s1a = 0.f, s2a = 0.f, s1b = 0.f, s2b = 0.f;
#pragma unroll
        for (int nf = 0; nf < 16; nf++) {
            s1a += C[nf][0] + C[nf][1];
            s2a += C[nf][0] * C[nf][0] + C[nf][1] * C[nf][1];
            s1b += C[nf][2] + C[nf][3];
            s2b += C[nf][2] * C[nf][2] + C[nf][3] * C[nf][3];
        }
#pragma unroll
        for (int o = 1; o <= 2; o <<= 1) {
            s1a += __shfl_xor_sync(0xffffffffu, s1a, o);
            s2a += __shfl_xor_sync(0xffffffffu, s2a, o);
            s1b += __shfl_xor_sync(0xffffffffu, s1b, o);
            s2b += __shfl_xor_sync(0xffffffffu, s2b, o);
        }
        if ((lane & 3) == 0)
            *(float4*)&red[sg][cg][crow][0] = make_float4(s1a, s2a, s1b, s2b);
        __syncthreads();

        float4 q0 = *(const float4*)&red[sg][0][crow][0];
        float4 q1 = *(const float4*)&red[sg][1][crow][0];
        float4 q2 = *(const float4*)&red[sg][2][crow][0];
        float4 q3 = *(const float4*)&red[sg][3][crow][0];
        float t1a = q0.x + q1.x + q2.x + q3.x;
        float t2a = q0.y + q1.y + q2.y + q3.y;
        float t1b = q0.z + q1.z + q2.z + q3.z;
        float t2b = q0.w + q1.w + q2.w + q3.w;
        float mu_a = t1a * (1.0f / NH);
        float va   = t2a * (1.0f / NH) - mu_a * mu_a;
        float rs_a = rsqrtf(va + 1e-5f);
        float mu_b = t1b * (1.0f / NH);
        float vb   = t2b * (1.0f / NH) - mu_b * mu_b;
        float rs_b = rsqrtf(vb + 1e-5f);

        // ---- gelu + accumulate over d ----
#pragma unroll
        for (int nf = 0; nf < 16; nf++) {
            int c0 = cg * 128 + nf * 8 + ccol;
            float2 gv = *(const float2*)&ws[34][c0];
            float2 ov = *(const float2*)&ws[35][c0];
            acc[nf][0] += fast_gelu((C[nf][0] - mu_a) * rs_a * gv.x + ov.x);
            acc[nf][1] += fast_gelu((C[nf][1] - mu_a) * rs_a * gv.y + ov.y);
            acc[nf][2] += fast_gelu((C[nf][2] - mu_b) * rs_b * gv.x + ov.x);
            acc[nf][3] += fast_gelu((C[nf][3] - mu_b) * rs_b * gv.y + ov.y);
        }
    }

    // ---- write acc -> g_mid ----
    int s0 = base + r0;
    int s1r = s0 + 8;
#pragma unroll
    for (int nf = 0; nf < 16; nf++) {
        int c0 = cg * 128 + nf * 8 + ccol;
        if (s0 < cnt)
            *(float2*)&g_mid[(size_t)(e * NB + s0) * NH + c0] =
                make_float2(acc[nf][0], acc[nf][1]);
        if (s1r < cnt)
            *(float2*)&g_mid[(size_t)(e * NB + s1r) * NH + c0] =
                make_float2(acc[nf][2], acc[nf][3]);
    }
}

// ---------------- stage 2: per-expert GEMM via TF32 mma.sync (kept) ---------
#define BM 128
#define BN 128
#define BK 16
__global__ __launch_bounds__(256, 2) void k_stage2(
    const float* __restrict__ wo, const float* __restrict__ bo,
    float* __restrict__ out) {
    int e = blockIdx.z;
    int cnt = g_count[e];
    int rowbase = blockIdx.x * BM;
    if (rowbase >= cnt) return;
    int colbase = blockIdx.y * BN;

    __shared__ unsigned As[2][BK][BM + 4];
    __shared__ unsigned Bs[2][BK][BN + 4];

    int tid = threadIdx.x;
    int warp = tid >> 5, lane = tid & 31;
    int wm = warp >> 1, wn = warp & 1;

    float C[2][8][4];
#pragma unroll
    for (int mi = 0; mi < 2; mi++)
#pragma unroll
        for (int ni = 0; ni < 8; ni++)
#pragma unroll
            for (int q = 0; q < 4; q++) C[mi][ni][q] = 0.0f;

    const float* mide = g_mid + (size_t)e * NB * NH;
    const float* woe  = wo + (size_t)e * NH * NH;

    int a_r  = tid >> 2, a_kq = tid & 3;
    int b_c4 = tid & 31, b_kk = tid >> 5;
    int gr0 = rowbase + a_r, gr1 = gr0 + 64;

    float4 pa[2], pb[2];
    pa[0] = (gr0 < cnt) ? *(const float4*)(mide + (size_t)gr0 * NH + a_kq * 4)
                        : make_float4(0.f, 0.f, 0.f, 0.f);
    pa[1] = (gr1 < cnt) ? *(const float4*)(mide + (size_t)gr1 * NH + a_kq * 4)
                        : make_float4(0.f, 0.f, 0.f, 0.f);
    pb[0] = *(const float4*)(woe + (size_t)b_kk * NH + colbase + b_c4 * 4);
    pb[1] = *(const float4*)(woe + (size_t)(b_kk + 8) * NH + colbase + b_c4 * 4);
#pragma unroll
    for (int q = 0; q < 2; q++) {
        int r = (q == 0) ? a_r : a_r + 64;
        As[0][a_kq * 4 + 0][r] = f2tf32(q == 0 ? pa[0].x : pa[1].x);
        As[0][a_kq * 4 + 1][r] = f2tf32(q == 0 ? pa[0].y : pa[1].y);
        As[0][a_kq * 4 + 2][r] = f2tf32(q == 0 ? pa[0].z : pa[1].z);
        As[0][a_kq * 4 + 3][r] = f2tf32(q == 0 ? pa[0].w : pa[1].w);
        int kk = (q == 0) ? b_kk : b_kk + 8;
        Bs[0][kk][b_c4 * 4 + 0] = f2tf32(q == 0 ? pb[0].x : pb[1].x);
        Bs[0][kk][b_c4 * 4 + 1] = f2tf32(q == 0 ? pb[0].y : pb[1].y);
        Bs[0][kk][b_c4 * 4 + 2] = f2tf32(q == 0 ? pb[0].z : pb[1].z);
        Bs[0][kk][b_c4 * 4 + 3] = f2tf32(q == 0 ? pb[0].w : pb[1].w);
    }
    __syncthreads();

    int arow = lane >> 2, acol = lane & 3;
    int brow = lane & 3,  bcol = lane >> 2;

#pragma unroll 1
    for (int t = 0; t < NH / BK; t++) {
        int p = t & 1;
        int k1 = (t + 1) * BK;
        bool hasnext = k1 < NH;
        if (hasnext) {
            pa[0] = (gr0 < cnt) ? *(const float4*)(mide + (size_t)gr0 * NH + k1 + a_kq * 4)
                                : make_float4(0.f, 0.f, 0.f, 0.f);
            pa[1] = (gr1 < cnt) ? *(const float4*)(mide + (size_t)gr1 * NH + k1 + a_kq * 4)
                                : make_float4(0.f, 0.f, 0.f, 0.f);
            pb[0] = *(const float4*)(woe + (size_t)(k1 + b_kk) * NH + colbase + b_c4 * 4);
            pb[1] = *(const float4*)(woe + (size_t)(k1 + b_kk + 8) * NH + colbase + b_c4 * 4);
        }

#pragma unroll
        for (int kc = 0; kc < BK; kc += 8) {
            unsigned afr[2][4];
#pragma unroll
            for (int mi = 0; mi < 2; mi++) {
                int m = wm * 32 + mi * 16 + arow;
                afr[mi][0] = As[p][kc + acol][m];
                afr[mi][1] = As[p][kc + acol][m + 8];
                afr[mi][2] = As[p][kc + acol + 4][m];
                afr[mi][3] = As[p][kc + acol + 4][m + 8];
            }
            unsigned bfr[8][2];
#pragma unroll
            for (int ni = 0; ni < 8; ni++) {
                int n = wn * 64 + ni * 8 + bcol;
                bfr[ni][0] = Bs[p][kc + brow][n];
                bfr[ni][1] = Bs[p][kc + brow + 4][n];
            }
#pragma unroll
            for (int mi = 0; mi < 2; mi++)
#pragma unroll
                for (int ni = 0; ni < 8; ni++)
                    mma_tf32(C[mi][ni], afr[mi], bfr[ni]);
        }

        if (hasnext) {
            int u = 1 - p;
#pragma unroll
            for (int q = 0; q < 2; q++) {
                int r = (q == 0) ? a_r : a_r + 64;
                As[u][a_kq * 4 + 0][r] = f2tf32(q == 0 ? pa[0].x : pa[1].x);
                As[u][a_kq * 4 + 1][r] = f2tf32(q == 0 ? pa[0].y : pa[1].y);
                As[u][a_kq * 4 + 2][r] = f2tf32(q == 0 ? pa[0].z : pa[1].z);
                As[u][a_kq * 4 + 3][r] = f2tf32(q == 0 ? pa[0].w : pa[1].w);
                int kk = (q == 0) ? b_kk : b_kk + 8;
                Bs[u][kk][b_c4 * 4 + 0] = f2tf32(q == 0 ? pb[0].x : pb[1].x);
                Bs[u][kk][b_c4 * 4 + 1] = f2tf32(q == 0 ? pb[0].y : pb[1].y);
                Bs[u][kk][b_c4 * 4 + 2] = f2tf32(q == 0 ? pb[0].z : pb[1].z);
                Bs[u][kk][b_c4 * 4 + 3] = f2tf32(q == 0 ? pb[0].w : pb[1].w);
            }
            __syncthreads();
        }
    }

    const float* boe = bo + (size_t)e * NH + colbase;
    int crow = lane >> 2, ccol = (lane & 3) * 2;
#pragma unroll
    for (int mi = 0; mi < 2; mi++) {
#pragma unroll
        for (int half = 0; half < 2; half++) {
            int r = wm * 32 + mi * 16 + crow + half * 8;
            int s = rowbase + r;
            if (s < cnt) {
                int b = g_rows[e * NB + s];
                float g = g_gate[e * NB + s];
                float* o = out + (size_t)b * NH + colbase;
#pragma unroll
                for (int ni = 0; ni < 8; ni++) {
                    int col = wn * 64 + ni * 8 + ccol;
                    float2 bo2 = __ldg((const float2*)(boe + col));
                    atomicAdd(o + col,     g * (C[mi][ni][half * 2 + 0] + bo2.x));
                    atomicAdd(o + col + 1, g * (C[mi][ni][half * 2 + 1] + bo2.y));
                }
            }
        }
    }
}

// ---------------- launch ----------------
extern "C" void kernel_launch(void* const* d_in, const int* in_sizes, int n_in,
                              void* d_out, int out_size) {
    const float* gate_input   = (const float*)d_in[0];
    const float* expert_input = (const float*)d_in[1];
    const int*   task_bh      = (const int*)  d_in[2];
    const float* gate_w       = (const float*)d_in[3];
    const float* gate_b       = (const float*)d_in[4];
    const float* freqs        = (const float*)d_in[5];
    const float* w1           = (const float*)d_in[6];
    const float* b1           = (const float*)d_in[7];
    const float* ln_g         = (const float*)d_in[8];
    const float* ln_b         = (const float*)d_in[9];
    const float* wo           = (const float*)d_in[10];
    const float* bo           = (const float*)d_in[11];
    float* out = (float*)d_out;

    cudaFuncSetAttribute(k_stage1, cudaFuncAttributeMaxDynamicSharedMemorySize,
                         S1_SMEM);

    k_init<<<1024, 256>>>(out, out_size);
    k_pack<<<dim3(ND, NE), 256>>>(w1, b1, ln_g, ln_b);
    k_gate<<<NB / 256, 256>>>(gate_input, task_bh, gate_w, gate_b);
    k_stage1<<<dim3(NB / S1S, NE), 256, S1_SMEM>>>(expert_input, freqs, w1);
    k_stage2<<<dim3(NB / BM, NH / BN, NE), 256>>>(wo, bo, out);
}